// round 2
// baseline (speedup 1.0000x reference)
#include <cuda_runtime.h>
#include <cstdint>

// Problem shape (fixed by the dataset)
#define MT 8192          // B*S
#define NT 4096          // D_OUT
#define KT 4096          // D_IN
#define K4 (KT / 4)      // 1024 packed int32 per row

// GEMM tiling
#define BM 128
#define BN 128
#define BK4 16           // 16 int32 = 64 int8 along K per stage
#define TM 8
#define TN 8
#define NSTAGE (K4 / BK4)  // 64

// Scratch for packed int8 operands (static device globals: allowed, no allocs)
__device__ __align__(16) int g_aq[(size_t)MT * K4];   // 32 MB
__device__ __align__(16) int g_wq[(size_t)NT * K4];   // 16 MB

// ---------------------------------------------------------------------------
// Pre-pass 1: quantize x (fp32) -> packed int8 in g_aq.
// Matches reference: clip(round(x / input_scale), -128, 127).
// rintf = round-half-to-even (same as jnp.round); true IEEE division to match
// the reference's halfway-case behavior.
// ---------------------------------------------------------------------------
__global__ void quant_pack_x_kernel(const float4* __restrict__ x,
                                    const float* __restrict__ in_scale,
                                    int n4) {
    int i = blockIdx.x * blockDim.x + threadIdx.x;
    if (i >= n4) return;
    float s = *in_scale;
    float4 v = x[i];
    int a0 = (int)fminf(fmaxf(rintf(v.x / s), -128.0f), 127.0f);
    int a1 = (int)fminf(fmaxf(rintf(v.y / s), -128.0f), 127.0f);
    int a2 = (int)fminf(fmaxf(rintf(v.z / s), -128.0f), 127.0f);
    int a3 = (int)fminf(fmaxf(rintf(v.w / s), -128.0f), 127.0f);
    g_aq[i] = (a0 & 0xFF) | ((a1 & 0xFF) << 8) | ((a2 & 0xFF) << 16) | ((a3 & 0xFF) << 24);
}

// ---------------------------------------------------------------------------
// Pre-pass 2: repack weight (int32 holding int8 values) -> packed int8 in g_wq.
// ---------------------------------------------------------------------------
__global__ void pack_w_kernel(const int4* __restrict__ w, int n4) {
    int i = blockIdx.x * blockDim.x + threadIdx.x;
    if (i >= n4) return;
    int4 v = w[i];
    g_wq[i] = (v.x & 0xFF) | ((v.y & 0xFF) << 8) | ((v.z & 0xFF) << 16) | ((v.w & 0xFF) << 24);
}

// ---------------------------------------------------------------------------
// int8 GEMM via dp4a: C[m,n] = (sum_k4 dp4a(Aq[m,k4], Wq[n,k4])) * (is*ws)
// Exact integer accumulation (|acc| <= 128*128*4096 < 2^31).
// ---------------------------------------------------------------------------
__global__ __launch_bounds__(256, 2)
void gemm_dp4a_kernel(float* __restrict__ C,
                      const float* __restrict__ w_scale,
                      const float* __restrict__ in_scale) {
    __shared__ __align__(16) int As[BM][BK4];   // [m][k4] : frag reads broadcast over tx
    __shared__ __align__(16) int Bs[BK4][BN];   // [k4][n] : frag reads vectorized over tx

    const int tiles_m = MT / BM;                // 64; bm fastest -> L2 reuse of A and B
    const int bm = blockIdx.x % tiles_m;
    const int bn = blockIdx.x / tiles_m;

    const int tid = threadIdx.x;
    const int tx = tid & 15;                    // 16 threads over N
    const int ty = tid >> 4;                    // 16 threads over M

    const int* __restrict__ Ab = g_aq + (size_t)(bm * BM) * K4;
    const int* __restrict__ Bb = g_wq + (size_t)(bn * BN) * K4;

    // Staging map: 512 int4 vectors per tile, 2 per thread.
    const int r0 = tid >> 2;        // rows 0..63
    const int c0 = tid & 3;         // which 16B chunk of the 64B tile row
    const int r1 = r0 + 64;         // rows 64..127

    int acc[TM][TN];
#pragma unroll
    for (int i = 0; i < TM; ++i)
#pragma unroll
        for (int j = 0; j < TN; ++j) acc[i][j] = 0;

    // Prologue loads (tile 0)
    int4 a0 = ((const int4*)(Ab + (size_t)r0 * K4))[c0];
    int4 a1 = ((const int4*)(Ab + (size_t)r1 * K4))[c0];
    int4 b0 = ((const int4*)(Bb + (size_t)r0 * K4))[c0];
    int4 b1 = ((const int4*)(Bb + (size_t)r1 * K4))[c0];

    for (int kt = 0; kt < NSTAGE; ++kt) {
        // Commit staged registers to smem
        *(int4*)&As[r0][c0 * 4] = a0;
        *(int4*)&As[r1][c0 * 4] = a1;
        const int kc = c0 * 4;
        Bs[kc + 0][r0] = b0.x; Bs[kc + 1][r0] = b0.y;
        Bs[kc + 2][r0] = b0.z; Bs[kc + 3][r0] = b0.w;
        Bs[kc + 0][r1] = b1.x; Bs[kc + 1][r1] = b1.y;
        Bs[kc + 2][r1] = b1.z; Bs[kc + 3][r1] = b1.w;
        __syncthreads();

        // Issue next tile's global loads early; 1024 dp4a below hide the latency
        if (kt + 1 < NSTAGE) {
            const int kof = (kt + 1) * BK4;
            a0 = ((const int4*)(Ab + (size_t)r0 * K4 + kof))[c0];
            a1 = ((const int4*)(Ab + (size_t)r1 * K4 + kof))[c0];
            b0 = ((const int4*)(Bb + (size_t)r0 * K4 + kof))[c0];
            b1 = ((const int4*)(Bb + (size_t)r1 * K4 + kof))[c0];
        }

#pragma unroll
        for (int k = 0; k < BK4; ++k) {
            int af[TM], bf[TN];
#pragma unroll
            for (int i = 0; i < TM; ++i) af[i] = As[ty * TM + i][k];
            int4 bv0 = *(const int4*)&Bs[k][tx * TN];
            int4 bv1 = *(const int4*)&Bs[k][tx * TN + 4];
            bf[0] = bv0.x; bf[1] = bv0.y; bf[2] = bv0.z; bf[3] = bv0.w;
            bf[4] = bv1.x; bf[5] = bv1.y; bf[6] = bv1.z; bf[7] = bv1.w;
#pragma unroll
            for (int i = 0; i < TM; ++i)
#pragma unroll
                for (int j = 0; j < TN; ++j)
                    acc[i][j] = __dp4a(af[i], bf[j], acc[i][j]);
        }
        __syncthreads();
    }

    // Epilogue: exact int32 -> fp32, combined scale
    const float sc = (*w_scale) * (*in_scale);
    const int m0 = bm * BM + ty * TM;
    const int n0 = bn * BN + tx * TN;
#pragma unroll
    for (int i = 0; i < TM; ++i) {
        float4 o0, o1;
        o0.x = (float)acc[i][0] * sc; o0.y = (float)acc[i][1] * sc;
        o0.z = (float)acc[i][2] * sc; o0.w = (float)acc[i][3] * sc;
        o1.x = (float)acc[i][4] * sc; o1.y = (float)acc[i][5] * sc;
        o1.z = (float)acc[i][6] * sc; o1.w = (float)acc[i][7] * sc;
        float* crow = C + (size_t)(m0 + i) * NT + n0;
        *(float4*)(crow)     = o0;
        *(float4*)(crow + 4) = o1;
    }
}

// ---------------------------------------------------------------------------
// Harness entry
// Inputs (metadata order): x fp32 [4,2048,4096], weight int32 [4096,4096],
//                          scale fp32 [1], input_scale fp32 [1]
// Output: fp32 [4,2048,4096]
// ---------------------------------------------------------------------------
extern "C" void kernel_launch(void* const* d_in, const int* in_sizes, int n_in,
                              void* d_out, int out_size) {
    const float* x        = (const float*)d_in[0];
    const int*   w        = (const int*)d_in[1];
    const float* w_scale  = (const float*)d_in[2];
    const float* in_scale = (const float*)d_in[3];
    float* out = (float*)d_out;

    (void)in_sizes; (void)n_in; (void)out_size;

    const int n4x = MT * K4;   // 8,388,608 packed words
    const int n4w = NT * K4;   // 4,194,304 packed words

    quant_pack_x_kernel<<<(n4x + 255) / 256, 256>>>((const float4*)x, in_scale, n4x);
    pack_w_kernel<<<(n4w + 255) / 256, 256>>>((const int4*)w, n4w);

    const int grid = (MT / BM) * (NT / BN);   // 64 * 32 = 2048
    gemm_dp4a_kernel<<<grid, 256>>>(out, w_scale, in_scale);
}

// round 5
// speedup vs baseline: 1.0889x; 1.0889x over previous
#include <cuda_runtime.h>
#include <cstdint>

// Problem shape (fixed by the dataset)
#define MT 8192
#define NT 4096
#define KTOT 4096
#define K4 (KTOT / 4)     // 1024 packed int32 per row

// GEMM tiling
#define BM 128
#define BN 256
#define BKB 64            // K-bytes per stage (16 int32 words)
#define NITER (KTOT / BKB)   // 64 mainloop iterations
#define NBUF 4
#define STAGE_BYTES ((BM + BN) * BKB)   // 24576
#define SMEM_TOTAL (NBUF * STAGE_BYTES) // 98304

// Packed int8 operands (static device globals — no allocs)
__device__ __align__(16) int g_aq[(size_t)MT * K4];   // 32 MB
__device__ __align__(16) int g_wq[(size_t)NT * K4];   // 16 MB

// ---------------------------------------------------------------------------
// PTX helpers
// ---------------------------------------------------------------------------
__device__ __forceinline__ uint32_t smem_u32(const void* p) {
    uint32_t a;
    asm("{ .reg .u64 t; cvta.to.shared.u64 t, %1; cvt.u32.u64 %0, t; }" : "=r"(a) : "l"(p));
    return a;
}
#define CP_ASYNC16(dst, src) \
    asm volatile("cp.async.cg.shared.global [%0], [%1], 16;" :: "r"(dst), "l"(src) : "memory")
#define CP_COMMIT()  asm volatile("cp.async.commit_group;" ::: "memory")
#define CP_WAIT(n)   asm volatile("cp.async.wait_group %0;" :: "n"(n) : "memory")

__device__ __forceinline__ void ldsm_x4(uint32_t& r0, uint32_t& r1, uint32_t& r2, uint32_t& r3,
                                        uint32_t addr) {
    asm volatile("ldmatrix.sync.aligned.m8n8.x4.shared.b16 {%0,%1,%2,%3}, [%4];"
                 : "=r"(r0), "=r"(r1), "=r"(r2), "=r"(r3) : "r"(addr));
}
__device__ __forceinline__ void mma_s8(int* c, const uint32_t* a, const uint32_t* b) {
    asm volatile(
        "mma.sync.aligned.m16n8k32.row.col.s32.s8.s8.s32 "
        "{%0,%1,%2,%3}, {%4,%5,%6,%7}, {%8,%9}, {%0,%1,%2,%3};"
        : "+r"(c[0]), "+r"(c[1]), "+r"(c[2]), "+r"(c[3])
        : "r"(a[0]), "r"(a[1]), "r"(a[2]), "r"(a[3]), "r"(b[0]), "r"(b[1]));
}

// ---------------------------------------------------------------------------
// Pre-pass 1: quantize x (fp32) -> packed int8. Matches reference:
// clip(round(x / input_scale), -128, 127); rintf = round-half-even like jnp.
// ---------------------------------------------------------------------------
__global__ void quant_pack_x_kernel(const float4* __restrict__ x,
                                    const float* __restrict__ in_scale, int n4) {
    int i = blockIdx.x * blockDim.x + threadIdx.x;
    if (i >= n4) return;
    float s = *in_scale;
    float4 v = x[i];
    int a0 = (int)fminf(fmaxf(rintf(v.x / s), -128.0f), 127.0f);
    int a1 = (int)fminf(fmaxf(rintf(v.y / s), -128.0f), 127.0f);
    int a2 = (int)fminf(fmaxf(rintf(v.z / s), -128.0f), 127.0f);
    int a3 = (int)fminf(fmaxf(rintf(v.w / s), -128.0f), 127.0f);
    g_aq[i] = (a0 & 0xFF) | ((a1 & 0xFF) << 8) | ((a2 & 0xFF) << 16) | ((a3 & 0xFF) << 24);
}

// Pre-pass 2: weight int32 (int8 range) -> packed int8
__global__ void pack_w_kernel(const int4* __restrict__ w, int n4) {
    int i = blockIdx.x * blockDim.x + threadIdx.x;
    if (i >= n4) return;
    int4 v = w[i];
    g_wq[i] = (v.x & 0xFF) | ((v.y & 0xFF) << 8) | ((v.z & 0xFF) << 16) | ((v.w & 0xFF) << 24);
}

// ---------------------------------------------------------------------------
// IMMA GEMM: C[m,n] = sum_k Aq[m,k]*Wq[n,k] (exact int32), then * (is*ws).
// BM=128 x BN=256 per CTA, 512 threads = 4(m) x 4(n) warps of 32x64.
// Smem tiles: 64-byte rows (4x 16B chunks), chunk swizzle c ^= (row>>1)&3
// -> conflict-free ldmatrix; stage s at s*24576, A then B (at +8192).
// ---------------------------------------------------------------------------
extern __shared__ char dyn_smem[];

__global__ __launch_bounds__(512, 1)
void gemm_imma_kernel(float* __restrict__ C,
                      const float* __restrict__ w_scale,
                      const float* __restrict__ in_scale) {
    const uint32_t sb = smem_u32(dyn_smem);
    const int tid = threadIdx.x;
    const int wid = tid >> 5;
    const int lid = tid & 31;
    const int mw = wid >> 2;          // 0..3  (32 rows each)
    const int nw = wid & 3;           // 0..3  (64 cols each)

    const int tiles_m = MT / BM;      // 64, bm-fastest for L2 reuse of B panel
    const int bm = blockIdx.x % tiles_m;
    const int bn = blockIdx.x / tiles_m;

    const int* __restrict__ Ab = g_aq + (size_t)(bm * BM) * K4;
    const int* __restrict__ Bb = g_wq + (size_t)(bn * BN) * K4;

    // ---- cp.async staging: 1536 chunks of 16B per stage, 3 per thread ----
    auto load_stage = [&](int kt, int buf) {
        const uint32_t base = sb + buf * STAGE_BYTES;
        const int kof = kt * 16;      // words
#pragma unroll
        for (int it = 0; it < 3; ++it) {
            int q = tid + it * 512;
            int row, c;
            uint32_t dst;
            const int* src;
            if (q < 512) {            // A: 128 rows x 4 chunks
                row = q >> 2; c = q & 3;
                dst = base + row * 64 + ((c ^ ((row >> 1) & 3)) << 4);
                src = Ab + (size_t)row * K4 + kof + c * 4;
            } else {                  // B: 256 rows x 4 chunks
                int p = q - 512;
                row = p >> 2; c = p & 3;
                dst = base + BM * BKB + row * 64 + ((c ^ ((row >> 1) & 3)) << 4);
                src = Bb + (size_t)row * K4 + kof + c * 4;
            }
            CP_ASYNC16(dst, src);
        }
        CP_COMMIT();
    };

    // ---- per-lane ldmatrix row/chunk precompute ----
    // A (m16 tiles): lanes 0-7 rows 0-7 / 8-15 rows 8-15 (chunk cb=0),
    //                lanes 16-31 same rows (chunk cb=1)
    const int rlA = lid & 15;
    const int cbA = lid >> 4;
    // B (two n8 tiles per ldmatrix.x4): lanes 0-15 rows 0-7 (cb 0 then 1),
    //                                   lanes 16-31 rows 8-15
    const int rlB = (lid & 7) | ((lid >> 4) << 3);
    const int cbB = (lid >> 3) & 1;

    uint32_t aoff[2]; int asr[2];
#pragma unroll
    for (int mi = 0; mi < 2; ++mi) {
        int r = mw * 32 + mi * 16 + rlA;
        aoff[mi] = r * 64; asr[mi] = (r >> 1) & 3;
    }
    uint32_t boff[4]; int bsr[4];
#pragma unroll
    for (int np = 0; np < 4; ++np) {
        int r = nw * 64 + np * 16 + rlB;
        boff[np] = BM * BKB + r * 64; bsr[np] = (r >> 1) & 3;
    }

    int acc[2][8][4];
#pragma unroll
    for (int mi = 0; mi < 2; ++mi)
#pragma unroll
        for (int nt = 0; nt < 8; ++nt)
#pragma unroll
            for (int j = 0; j < 4; ++j) acc[mi][nt][j] = 0;

    // ---- pipeline prologue ----
    load_stage(0, 0);
    load_stage(1, 1);
    load_stage(2, 2);

    for (int kt = 0; kt < NITER; ++kt) {
        if (kt < NITER - 2)      { CP_WAIT(2); }
        else if (kt == NITER - 2){ CP_WAIT(1); }
        else                     { CP_WAIT(0); }
        __syncthreads();

        if (kt + 3 < NITER) load_stage(kt + 3, (kt + 3) & (NBUF - 1));

        const uint32_t stage = sb + (kt & (NBUF - 1)) * STAGE_BYTES;
#pragma unroll
        for (int ks = 0; ks < 2; ++ks) {
            uint32_t af[2][4], bf[8][2];
            const int cA = 2 * ks + cbA;
            const int cB = 2 * ks + cbB;
#pragma unroll
            for (int mi = 0; mi < 2; ++mi)
                ldsm_x4(af[mi][0], af[mi][1], af[mi][2], af[mi][3],
                        stage + aoff[mi] + ((cA ^ asr[mi]) << 4));
#pragma unroll
            for (int np = 0; np < 4; ++np) {
                uint32_t r0, r1, r2, r3;
                ldsm_x4(r0, r1, r2, r3, stage + boff[np] + ((cB ^ bsr[np]) << 4));
                bf[np * 2 + 0][0] = r0; bf[np * 2 + 0][1] = r1;
                bf[np * 2 + 1][0] = r2; bf[np * 2 + 1][1] = r3;
            }
#pragma unroll
            for (int mi = 0; mi < 2; ++mi)
#pragma unroll
                for (int nt = 0; nt < 8; ++nt)
                    mma_s8(acc[mi][nt], af[mi], bf[nt]);
        }
    }

    // ---- epilogue: exact int32 -> fp32 with combined scale ----
    const float sc = (*w_scale) * (*in_scale);
    const int g = lid >> 2, tig = lid & 3;
    const int m_base = bm * BM + mw * 32;
    const int n_base = bn * BN + nw * 64;
#pragma unroll
    for (int mi = 0; mi < 2; ++mi) {
#pragma unroll
        for (int nt = 0; nt < 8; ++nt) {
            const int r0 = m_base + mi * 16 + g;
            const int col = n_base + nt * 8 + 2 * tig;
            float2 v0, v1;
            v0.x = (float)acc[mi][nt][0] * sc; v0.y = (float)acc[mi][nt][1] * sc;
            v1.x = (float)acc[mi][nt][2] * sc; v1.y = (float)acc[mi][nt][3] * sc;
            *(float2*)(C + (size_t)r0 * NT + col)       = v0;
            *(float2*)(C + (size_t)(r0 + 8) * NT + col) = v1;
        }
    }
}

// ---------------------------------------------------------------------------
// Harness entry
// Inputs: x fp32 [4,2048,4096], weight int32 [4096,4096], scale [1], input_scale [1]
// Output: fp32 [4,2048,4096]
// ---------------------------------------------------------------------------
extern "C" void kernel_launch(void* const* d_in, const int* in_sizes, int n_in,
                              void* d_out, int out_size) {
    const float* x        = (const float*)d_in[0];
    const int*   w        = (const int*)d_in[1];
    const float* w_scale  = (const float*)d_in[2];
    const float* in_scale = (const float*)d_in[3];
    float* out = (float*)d_out;
    (void)in_sizes; (void)n_in; (void)out_size;

    cudaFuncSetAttribute(gemm_imma_kernel,
                         cudaFuncAttributeMaxDynamicSharedMemorySize, SMEM_TOTAL);

    const int n4x = MT * K4;   // 8,388,608
    const int n4w = NT * K4;   // 4,194,304
    quant_pack_x_kernel<<<(n4x + 255) / 256, 256>>>((const float4*)x, in_scale, n4x);
    pack_w_kernel<<<(n4w + 255) / 256, 256>>>((const int4*)w, n4w);

    const int grid = (MT / BM) * (NT / BN);   // 64 * 16 = 1024
    gemm_imma_kernel<<<grid, 512, SMEM_TOTAL>>>(out, w_scale, in_scale);
}

// round 6
// speedup vs baseline: 3.0624x; 2.8123x over previous
#include <cuda_runtime.h>
#include <cuda_bf16.h>
#include <cstdint>

// Problem shape (fixed by the dataset)
#define MT 8192
#define NT 4096
#define KTOT 4096

// GEMM tiling
#define BM 128
#define BN 256
#define BK 64                 // bf16 elems per stage -> 128B rows
#define NITER (KTOT / BK)     // 64
#define NBUF 3
#define STAGE_BYTES ((BM + BN) * BK * 2)   // 49152
#define SMEM_TOTAL (NBUF * STAGE_BYTES)    // 147456

// Packed bf16 operands (static device globals — no allocs)
__device__ __align__(16) __nv_bfloat16 g_a[(size_t)MT * KTOT];  // 64 MB
__device__ __align__(16) __nv_bfloat16 g_w[(size_t)NT * KTOT];  // 32 MB

// ---------------------------------------------------------------------------
// PTX helpers (baseline-PTX only: cp.async, ldmatrix, mma.sync bf16)
// ---------------------------------------------------------------------------
__device__ __forceinline__ uint32_t smem_u32(const void* p) {
    uint32_t a;
    asm("{ .reg .u64 t; cvta.to.shared.u64 t, %1; cvt.u32.u64 %0, t; }" : "=r"(a) : "l"(p));
    return a;
}
#define CP_ASYNC16(dst, src) \
    asm volatile("cp.async.cg.shared.global [%0], [%1], 16;" :: "r"(dst), "l"(src) : "memory")
#define CP_COMMIT()  asm volatile("cp.async.commit_group;" ::: "memory")
#define CP_WAIT(n)   asm volatile("cp.async.wait_group %0;" :: "n"(n) : "memory")

// byte-offset swizzle for 128B rows (8 x 16B chunks): chunk ^= (row & 7)
#define SWZ(o) ((o) ^ (((o) >> 3) & 0x70))

__device__ __forceinline__ void ldsm_x4(uint32_t& r0, uint32_t& r1, uint32_t& r2, uint32_t& r3,
                                        uint32_t addr) {
    asm volatile("ldmatrix.sync.aligned.m8n8.x4.shared.b16 {%0,%1,%2,%3}, [%4];"
                 : "=r"(r0), "=r"(r1), "=r"(r2), "=r"(r3) : "r"(addr));
}
__device__ __forceinline__ void mma_bf16(float* c, const uint32_t* a, const uint32_t* b) {
    asm volatile(
        "mma.sync.aligned.m16n8k16.row.col.f32.bf16.bf16.f32 "
        "{%0,%1,%2,%3}, {%4,%5,%6,%7}, {%8,%9}, {%0,%1,%2,%3};"
        : "+f"(c[0]), "+f"(c[1]), "+f"(c[2]), "+f"(c[3])
        : "r"(a[0]), "r"(a[1]), "r"(a[2]), "r"(a[3]), "r"(b[0]), "r"(b[1]));
}

// ---------------------------------------------------------------------------
// Pre-pass 1: x fp32 -> quantized bf16 (integral values in [-128,127], exact).
// Matches reference: clip(round(x / input_scale), -128, 127); rintf = half-even.
// ---------------------------------------------------------------------------
__global__ void quant_pack_x_kernel(const float4* __restrict__ x,
                                    const float* __restrict__ in_scale, int n8) {
    int i = blockIdx.x * blockDim.x + threadIdx.x;
    if (i >= n8) return;
    float s = *in_scale;
    float4 v0 = x[i * 2], v1 = x[i * 2 + 1];
    __nv_bfloat16 o[8];
    o[0] = __float2bfloat16(fminf(fmaxf(rintf(v0.x / s), -128.0f), 127.0f));
    o[1] = __float2bfloat16(fminf(fmaxf(rintf(v0.y / s), -128.0f), 127.0f));
    o[2] = __float2bfloat16(fminf(fmaxf(rintf(v0.z / s), -128.0f), 127.0f));
    o[3] = __float2bfloat16(fminf(fmaxf(rintf(v0.w / s), -128.0f), 127.0f));
    o[4] = __float2bfloat16(fminf(fmaxf(rintf(v1.x / s), -128.0f), 127.0f));
    o[5] = __float2bfloat16(fminf(fmaxf(rintf(v1.y / s), -128.0f), 127.0f));
    o[6] = __float2bfloat16(fminf(fmaxf(rintf(v1.z / s), -128.0f), 127.0f));
    o[7] = __float2bfloat16(fminf(fmaxf(rintf(v1.w / s), -128.0f), 127.0f));
    *(uint4*)(g_a + (size_t)i * 8) = *(const uint4*)o;
}

// Pre-pass 2: weight int32 (int8 range) -> bf16 (exact)
__global__ void pack_w_kernel(const int4* __restrict__ w, int n8) {
    int i = blockIdx.x * blockDim.x + threadIdx.x;
    if (i >= n8) return;
    int4 v0 = w[i * 2], v1 = w[i * 2 + 1];
    __nv_bfloat16 o[8];
    o[0] = __float2bfloat16((float)v0.x);
    o[1] = __float2bfloat16((float)v0.y);
    o[2] = __float2bfloat16((float)v0.z);
    o[3] = __float2bfloat16((float)v0.w);
    o[4] = __float2bfloat16((float)v1.x);
    o[5] = __float2bfloat16((float)v1.y);
    o[6] = __float2bfloat16((float)v1.z);
    o[7] = __float2bfloat16((float)v1.w);
    *(uint4*)(g_w + (size_t)i * 8) = *(const uint4*)o;
}

// ---------------------------------------------------------------------------
// bf16 HMMA GEMM: C[m,n] = sum_k A[m,k]*W[n,k] (f32 acc), then * (is*ws).
// BM=128 x BN=256 per CTA, 512 threads = 4(m) x 4(n) warps of 32x64.
// Smem: 128B rows (8 x 16B chunks), SWZ swizzle; stage s at s*49152,
// A (128 rows) then B (256 rows at +16384).
// ---------------------------------------------------------------------------
extern __shared__ char dyn_smem[];

__global__ __launch_bounds__(512, 1)
void gemm_hmma_kernel(float* __restrict__ C,
                      const float* __restrict__ w_scale,
                      const float* __restrict__ in_scale) {
    const uint32_t sb = smem_u32(dyn_smem);
    const int tid = threadIdx.x;
    const int wid = tid >> 5;
    const int lid = tid & 31;
    const int mw = wid >> 2;          // 0..3  (32 rows each)
    const int nw = wid & 3;           // 0..3  (64 cols each)

    const int tiles_m = MT / BM;      // 64, bm-fastest for L2 reuse of B panel
    const int bm = blockIdx.x % tiles_m;
    const int bn = blockIdx.x / tiles_m;

    const __nv_bfloat16* __restrict__ Ab = g_a + (size_t)(bm * BM) * KTOT;
    const __nv_bfloat16* __restrict__ Bb = g_w + (size_t)(bn * BN) * KTOT;

    // ---- cp.async staging: 3072 chunks of 16B per stage, 6 per thread ----
    auto load_stage = [&](int kt, int buf) {
        const uint32_t base = sb + buf * STAGE_BYTES;
        const int kof = kt * BK;      // bf16 elems
#pragma unroll
        for (int it = 0; it < 6; ++it) {
            int q = tid + it * 512;
            uint32_t dst;
            const __nv_bfloat16* src;
            if (q < 1024) {           // A: 128 rows x 8 chunks
                int row = q >> 3, c = q & 7;
                dst = base + SWZ(row * 128 + c * 16);
                src = Ab + (size_t)row * KTOT + kof + c * 8;
            } else {                  // B: 256 rows x 8 chunks
                int p = q - 1024;
                int row = p >> 3, c = p & 7;
                dst = base + BM * BK * 2 + SWZ(row * 128 + c * 16);
                src = Bb + (size_t)row * KTOT + kof + c * 8;
            }
            CP_ASYNC16(dst, src);
        }
        CP_COMMIT();
    };

    // ---- per-lane ldmatrix row/chunk precompute ----
    // A x4 over m16 x k16: lanes 0-7 rows 0-7 (k0-7), 8-15 rows 8-15 (k0-7),
    //                      16-23 rows 0-7 (k8-15), 24-31 rows 8-15 (k8-15)
    const int rlA = lid & 15;
    const int cbA = lid >> 4;         // 0 or 1 (16B chunk within k16)
    // B x4 over n16 x k16: lanes 0-7 n0-7 (k0-7), 8-15 n0-7 (k8-15),
    //                      16-23 n8-15 (k0-7), 24-31 n8-15 (k8-15)
    const int rlB = (lid & 7) | ((lid >> 4) << 3);
    const int cbB = (lid >> 3) & 1;

    uint32_t aoff[2]; int asw[2];
#pragma unroll
    for (int mi = 0; mi < 2; ++mi) {
        int r = mw * 32 + mi * 16 + rlA;
        aoff[mi] = r * 128; asw[mi] = r & 7;
    }
    uint32_t boff[4]; int bsw[4];
#pragma unroll
    for (int np = 0; np < 4; ++np) {
        int r = nw * 64 + np * 16 + rlB;
        boff[np] = BM * BK * 2 + r * 128; bsw[np] = r & 7;
    }

    float acc[2][8][4];
#pragma unroll
    for (int mi = 0; mi < 2; ++mi)
#pragma unroll
        for (int nt = 0; nt < 8; ++nt)
#pragma unroll
            for (int j = 0; j < 4; ++j) acc[mi][nt][j] = 0.0f;

    // ---- pipeline prologue ----
    load_stage(0, 0);
    load_stage(1, 1);

    for (int kt = 0; kt < NITER; ++kt) {
        if (kt < NITER - 1) { CP_WAIT(1); } else { CP_WAIT(0); }
        __syncthreads();

        if (kt + 2 < NITER) load_stage(kt + 2, (kt + 2) % NBUF);

        const uint32_t stage = sb + (kt % NBUF) * STAGE_BYTES;
#pragma unroll
        for (int ks = 0; ks < 4; ++ks) {      // 4 k16 chunks per stage
            uint32_t af[2][4], bf[8][2];
            const int cA = 2 * ks + cbA;      // 16B chunk index 0..7
            const int cB = 2 * ks + cbB;
#pragma unroll
            for (int mi = 0; mi < 2; ++mi)
                ldsm_x4(af[mi][0], af[mi][1], af[mi][2], af[mi][3],
                        stage + aoff[mi] + ((cA ^ asw[mi]) << 4));
#pragma unroll
            for (int np = 0; np < 4; ++np) {
                uint32_t r0, r1, r2, r3;
                ldsm_x4(r0, r1, r2, r3, stage + boff[np] + ((cB ^ bsw[np]) << 4));
                bf[np * 2 + 0][0] = r0; bf[np * 2 + 0][1] = r1;
                bf[np * 2 + 1][0] = r2; bf[np * 2 + 1][1] = r3;
            }
#pragma unroll
            for (int mi = 0; mi < 2; ++mi)
#pragma unroll
                for (int nt = 0; nt < 8; ++nt)
                    mma_bf16(acc[mi][nt], af[mi], bf[nt]);
        }
    }

    // ---- epilogue: scale and store ----
    const float sc = (*w_scale) * (*in_scale);
    const int g = lid >> 2, tig = lid & 3;
    const int m_base = bm * BM + mw * 32;
    const int n_base = bn * BN + nw * 64;
#pragma unroll
    for (int mi = 0; mi < 2; ++mi) {
#pragma unroll
        for (int nt = 0; nt < 8; ++nt) {
            const int r0 = m_base + mi * 16 + g;
            const int col = n_base + nt * 8 + 2 * tig;
            float2 v0, v1;
            v0.x = acc[mi][nt][0] * sc; v0.y = acc[mi][nt][1] * sc;
            v1.x = acc[mi][nt][2] * sc; v1.y = acc[mi][nt][3] * sc;
            *(float2*)(C + (size_t)r0 * NT + col)       = v0;
            *(float2*)(C + (size_t)(r0 + 8) * NT + col) = v1;
        }
    }
}

// ---------------------------------------------------------------------------
// Harness entry
// Inputs: x fp32 [4,2048,4096], weight int32 [4096,4096], scale [1], input_scale [1]
// Output: fp32 [4,2048,4096]
// ---------------------------------------------------------------------------
extern "C" void kernel_launch(void* const* d_in, const int* in_sizes, int n_in,
                              void* d_out, int out_size) {
    const float* x        = (const float*)d_in[0];
    const int*   w        = (const int*)d_in[1];
    const float* w_scale  = (const float*)d_in[2];
    const float* in_scale = (const float*)d_in[3];
    float* out = (float*)d_out;
    (void)in_sizes; (void)n_in; (void)out_size;

    cudaFuncSetAttribute(gemm_hmma_kernel,
                         cudaFuncAttributeMaxDynamicSharedMemorySize, SMEM_TOTAL);

    const int n8x = MT * KTOT / 8;   // 4,194,304
    const int n8w = NT * KTOT / 8;   // 2,097,152
    quant_pack_x_kernel<<<(n8x + 255) / 256, 256>>>((const float4*)x, in_scale, n8x);
    pack_w_kernel<<<(n8w + 255) / 256, 256>>>((const int4*)w, n8w);

    const int grid = (MT / BM) * (NT / BN);   // 64 * 16 = 1024
    gemm_hmma_kernel<<<grid, 512, SMEM_TOTAL>>>(out, w_scale, in_scale);
}